// round 2
// baseline (speedup 1.0000x reference)
#include <cuda_runtime.h>
#include <cuda_bf16.h>
#include <cstdint>
#include <cstddef>

#define Bq 256
#define Tq 512
#define Dq 64
#define Hq 128
#define NROW (Bq * Tq)

// ---------------- scratch (device globals; no runtime allocation) ----------
__device__ float g_Az[(size_t)NROW * Hq];
__device__ float g_Ar[(size_t)NROW * Hq];
__device__ float g_Ah[(size_t)NROW * Hq];
__device__ float g_gh[(size_t)NROW * Hq];

// ---------------- Phase 1: imputation + input projections ------------------
// For each row (b,t):
//   gamma_x = exp(-relu(w_gamma_x*dlt + b_gamma_x))           [D]
//   x = m*x + (1-m)*(gamma_x*xl + (1-gamma_x)*mean)           [D]
//   gamma_h = exp(-relu(dlt @ w_gamma_h + b_gamma_h))         [H]
//   A_z = x @ w_zx + m @ w_zm + b_z                            [H]
//   A_r = x @ w_rx + m @ w_rm + b_r                            [H]
//   A_h = x @ w_hx + m @ w_hm + b_h                            [H]
#define RPB 16          // rows per block
#define P1_STRIDE 20    // padded row stride in smem (floats), 16B-multiple

__global__ void __launch_bounds__(128) phase1_kernel(
    const float* __restrict__ values, const float* __restrict__ masks,
    const float* __restrict__ deltas, const float* __restrict__ emp,
    const float* __restrict__ xlocf,
    const float* __restrict__ wgx, const float* __restrict__ bgx,
    const float* __restrict__ wgh, const float* __restrict__ bgh,
    const float* __restrict__ wzx, const float* __restrict__ wzm, const float* __restrict__ bz,
    const float* __restrict__ wrx, const float* __restrict__ wrm, const float* __restrict__ br,
    const float* __restrict__ whx, const float* __restrict__ whm, const float* __restrict__ bh)
{
    __shared__ float xs[Dq][P1_STRIDE];
    __shared__ float ms[Dq][P1_STRIDE];
    __shared__ float ds[Dq][P1_STRIDE];

    const int row0 = blockIdx.x * RPB;
    const int tid = threadIdx.x;

    // Load tile + impute on the fly. i -> (r = i>>6, k = i&63); coalesced.
    for (int i = tid; i < RPB * Dq; i += 128) {
        int r = i >> 6, k = i & 63;
        size_t g = (size_t)(row0 + r) * Dq + k;
        float x = values[g], m = masks[g], dl = deltas[g], xl = xlocf[g];
        float gx = __expf(-fmaxf(fmaf(wgx[k], dl, bgx[k]), 0.f));
        float xi = m * x + (1.f - m) * (gx * xl + (1.f - gx) * emp[k]);
        xs[k][r] = xi;
        ms[k][r] = m;
        ds[k][r] = dl;
    }
    __syncthreads();

    const int j = tid;  // output column 0..127
    float accZ[RPB], accR[RPB], accH[RPB], accG[RPB];
    {
        float bzv = bz[j], brv = br[j], bhv = bh[j], bgv = bgh[j];
#pragma unroll
        for (int r = 0; r < RPB; r++) { accZ[r] = bzv; accR[r] = brv; accH[r] = bhv; accG[r] = bgv; }
    }

#pragma unroll 4
    for (int k = 0; k < Dq; k++) {
        float wghv = wgh[k * Hq + j];
        float wzxv = wzx[k * Hq + j], wzmv = wzm[k * Hq + j];
        float wrxv = wrx[k * Hq + j], wrmv = wrm[k * Hq + j];
        float whxv = whx[k * Hq + j], whmv = whm[k * Hq + j];
        const float4* x4 = (const float4*)&xs[k][0];
        const float4* m4 = (const float4*)&ms[k][0];
        const float4* d4 = (const float4*)&ds[k][0];
#pragma unroll
        for (int rq = 0; rq < RPB / 4; rq++) {
            float4 xv = x4[rq], mv = m4[rq], dv = d4[rq];
            float xa[4] = {xv.x, xv.y, xv.z, xv.w};
            float ma[4] = {mv.x, mv.y, mv.z, mv.w};
            float da[4] = {dv.x, dv.y, dv.z, dv.w};
#pragma unroll
            for (int u = 0; u < 4; u++) {
                int r = rq * 4 + u;
                accG[r] = fmaf(da[u], wghv, accG[r]);
                accZ[r] = fmaf(xa[u], wzxv, accZ[r]);
                accZ[r] = fmaf(ma[u], wzmv, accZ[r]);
                accR[r] = fmaf(xa[u], wrxv, accR[r]);
                accR[r] = fmaf(ma[u], wrmv, accR[r]);
                accH[r] = fmaf(xa[u], whxv, accH[r]);
                accH[r] = fmaf(ma[u], whmv, accH[r]);
            }
        }
    }

#pragma unroll
    for (int r = 0; r < RPB; r++) {
        size_t o = (size_t)(row0 + r) * Hq + j;
        g_Az[o] = accZ[r];
        g_Ar[o] = accR[r];
        g_Ah[o] = accH[r];
        g_gh[o] = __expf(-fmaxf(accG[r], 0.f));
    }
}

// ---------------- Phase 2: persistent recurrence ---------------------------
// 128 CTAs, each owns 2 batch rows for all T steps. Weights in SMEM (192KB).
// Per step: h <- gamma_h*h;  z,r = sigmoid(A + h@W);  h~ = tanh(A_h + (r*h)@Whh);
//           h <- (1-z)h + z*h~.  Prefetch A(t+1) during compute.
#define RPC 2
#define GRID2 (Bq / RPC)
#define P2_SMEM_BYTES ((3 * Hq * Hq + 5 * RPC * Hq) * (int)sizeof(float))

__global__ void __launch_bounds__(256) phase2_kernel(
    const float* __restrict__ wzh, const float* __restrict__ wrh,
    const float* __restrict__ whh,
    float* __restrict__ hidden, float* __restrict__ hlast)
{
    extern __shared__ float sm[];
    float* sWz  = sm;                   // [Hq][Hq]
    float* sWr  = sWz + Hq * Hq;        // [Hq][Hq]
    float* sWh  = sWr + Hq * Hq;        // [Hq][Hq]
    float* hs   = sWh + Hq * Hq;        // [RPC][Hq] gamma-scaled h
    float* rhs_ = hs + RPC * Hq;        // [RPC][Hq] r*h
    float* zb   = rhs_ + RPC * Hq;      // [RPC][Hq] z
    float* sAz  = zb + RPC * Hq;        // [RPC][Hq]
    float* sAr  = sAz + RPC * Hq;       // [RPC][Hq]

    const int tid = threadIdx.x;
    const int b0 = blockIdx.x * RPC;

    // Load weights (each thread: 16 float4 per matrix, coalesced).
    for (int i = tid * 4; i < Hq * Hq; i += 256 * 4) {
        *(float4*)&sWz[i] = *(const float4*)&wzh[i];
        *(float4*)&sWr[i] = *(const float4*)&wrh[i];
        *(float4*)&sWh[i] = *(const float4*)&whh[i];
    }

    const int row = tid >> 7;     // 0..1 (also reused as gate id in z/r phase)
    const int j = tid & 127;

    float hreg = 0.f;
    size_t ab = ((size_t)(b0 + row) * Tq) * Hq + j;
    float az = g_Az[ab], ar = g_Ar[ab], ah = g_Ah[ab], gh = g_gh[ab];

    __syncthreads();  // weights visible

    for (int t = 0; t < Tq; t++) {
        // ---- stage: gamma-scale h, publish h and A to smem
        hreg *= gh;
        hs[row * Hq + j] = hreg;
        sAz[row * Hq + j] = az;
        sAr[row * Hq + j] = ar;
        float ah_cur = ah;

        // prefetch A(t+1) — consumed next iteration, hidden behind compute
        int tn = (t + 1 < Tq) ? (t + 1) : t;
        size_t an = ((size_t)(b0 + row) * Tq + tn) * Hq + j;
        az = g_Az[an]; ar = g_Ar[an]; ah = g_Ah[an]; gh = g_gh[an];

        __syncthreads();  // S1: hs/sA ready; also orders prev-iter smem reads

        // ---- z/r phase: thread = (gate = row, col = j); computes both rows
        {
            const float* W = row ? sWr : sWz;
            const float* sA = row ? sAr : sAz;
            float a0 = sA[0 * Hq + j];
            float a1 = sA[1 * Hq + j];
#pragma unroll
            for (int k = 0; k < Hq; k += 4) {
                float4 h0 = *(const float4*)&hs[0 * Hq + k];
                float4 h1 = *(const float4*)&hs[1 * Hq + k];
                float w0 = W[(k + 0) * Hq + j];
                float w1 = W[(k + 1) * Hq + j];
                float w2 = W[(k + 2) * Hq + j];
                float w3 = W[(k + 3) * Hq + j];
                a0 = fmaf(h0.x, w0, a0); a0 = fmaf(h0.y, w1, a0);
                a0 = fmaf(h0.z, w2, a0); a0 = fmaf(h0.w, w3, a0);
                a1 = fmaf(h1.x, w0, a1); a1 = fmaf(h1.y, w1, a1);
                a1 = fmaf(h1.z, w2, a1); a1 = fmaf(h1.w, w3, a1);
            }
            float s0 = 1.f / (1.f + __expf(-a0));
            float s1 = 1.f / (1.f + __expf(-a1));
            if (row == 0) {            // z gate
                zb[0 * Hq + j] = s0;
                zb[1 * Hq + j] = s1;
            } else {                   // r gate -> r*h
                rhs_[0 * Hq + j] = s0 * hs[0 * Hq + j];
                rhs_[1 * Hq + j] = s1 * hs[1 * Hq + j];
            }
        }
        __syncthreads();  // S2: zb / rhs ready

        // ---- h~ phase + update: thread = (row, j)
        {
            float acc = ah_cur;
#pragma unroll
            for (int k = 0; k < Hq; k += 4) {
                float4 rv = *(const float4*)&rhs_[row * Hq + k];
                acc = fmaf(rv.x, sWh[(k + 0) * Hq + j], acc);
                acc = fmaf(rv.y, sWh[(k + 1) * Hq + j], acc);
                acc = fmaf(rv.z, sWh[(k + 2) * Hq + j], acc);
                acc = fmaf(rv.w, sWh[(k + 3) * Hq + j], acc);
            }
            float htl = tanhf(acc);
            float z = zb[row * Hq + j];
            float hnew = fmaf(z, htl - hreg, hreg);  // (1-z)h + z*h~
            hreg = hnew;
            hidden[((size_t)(b0 + row) * Tq + t) * Hq + j] = hnew;
        }
        // next iteration's S1 orders ht-phase reads vs. next zr writes
    }
    hlast[(size_t)(b0 + row) * Hq + j] = hreg;
}

// ---------------- launch ----------------------------------------------------
extern "C" void kernel_launch(void* const* d_in, const int* in_sizes, int n_in,
                              void* d_out, int out_size) {
    const float* values = (const float*)d_in[0];
    const float* masks  = (const float*)d_in[1];
    const float* deltas = (const float*)d_in[2];
    const float* emp    = (const float*)d_in[3];
    const float* xlocf  = (const float*)d_in[4];
    const float* wgx    = (const float*)d_in[5];
    const float* wgh    = (const float*)d_in[6];
    const float* wrx    = (const float*)d_in[7];
    const float* wrh    = (const float*)d_in[8];
    const float* wrm    = (const float*)d_in[9];
    const float* wzx    = (const float*)d_in[10];
    const float* wzh    = (const float*)d_in[11];
    const float* wzm    = (const float*)d_in[12];
    const float* whx    = (const float*)d_in[13];
    const float* whh    = (const float*)d_in[14];
    const float* whm    = (const float*)d_in[15];
    const float* bgx    = (const float*)d_in[16];
    const float* bgh    = (const float*)d_in[17];
    const float* br     = (const float*)d_in[18];
    const float* bz     = (const float*)d_in[19];
    const float* bh     = (const float*)d_in[20];

    float* out = (float*)d_out;
    float* hidden = out;                              // [B, T, H]
    float* hlast = out + (size_t)Bq * Tq * Hq;        // [B, H]

    cudaFuncSetAttribute(phase2_kernel,
                         cudaFuncAttributeMaxDynamicSharedMemorySize,
                         P2_SMEM_BYTES);

    phase1_kernel<<<NROW / RPB, 128>>>(values, masks, deltas, emp, xlocf,
                                       wgx, bgx, wgh, bgh,
                                       wzx, wzm, bz,
                                       wrx, wrm, br,
                                       whx, whm, bh);

    phase2_kernel<<<GRID2, 256, P2_SMEM_BYTES>>>(wzh, wrh, whh, hidden, hlast);
}

// round 3
// speedup vs baseline: 1.2501x; 1.2501x over previous
#include <cuda_runtime.h>
#include <cuda_bf16.h>
#include <cstdint>
#include <cstddef>

#define Bq 256
#define Tq 512
#define Dq 64
#define Hq 128
#define NROW (Bq * Tq)

typedef unsigned long long ull;

// ---------------- packed f32x2 helpers -------------------------------------
__device__ __forceinline__ ull ffma2(ull a, ull b, ull c) {
    ull d;
    asm("fma.rn.f32x2 %0, %1, %2, %3;" : "=l"(d) : "l"(a), "l"(b), "l"(c));
    return d;
}
__device__ __forceinline__ ull pack2(float lo, float hi) {
    ull d;
    asm("mov.b64 %0, {%1, %2};" : "=l"(d) : "f"(lo), "f"(hi));
    return d;
}
__device__ __forceinline__ float2 unpack2(ull v) {
    float2 r;
    asm("mov.b64 {%0, %1}, %2;" : "=f"(r.x), "=f"(r.y) : "l"(v));
    return r;
}

// ---------------- scratch (device globals; no runtime allocation) ----------
__device__ float g_Az[(size_t)NROW * Hq];
__device__ float g_Ar[(size_t)NROW * Hq];
__device__ float g_Ah[(size_t)NROW * Hq];
__device__ float g_gh[(size_t)NROW * Hq];

// ---------------- Phase 1: imputation + input projections ------------------
// 32 rows per CTA, 256 threads. thread = (j = tid&127, half = tid>>7).
// Each thread computes 16 rows (8 f32x2 row-pairs) for output column j of
// A_z, A_r, A_h, gamma_h-preact, using packed FFMA2 with broadcast weights.
#define RPB 32

__global__ void __launch_bounds__(256) phase1_kernel(
    const float* __restrict__ values, const float* __restrict__ masks,
    const float* __restrict__ deltas, const float* __restrict__ emp,
    const float* __restrict__ xlocf,
    const float* __restrict__ wgx, const float* __restrict__ bgx,
    const float* __restrict__ wgh, const float* __restrict__ bgh,
    const float* __restrict__ wzx, const float* __restrict__ wzm, const float* __restrict__ bz,
    const float* __restrict__ wrx, const float* __restrict__ wrm, const float* __restrict__ br,
    const float* __restrict__ whx, const float* __restrict__ whm, const float* __restrict__ bh)
{
    // pair-interleaved inputs: element r of row k lives at float index r
    __shared__ float2 xp[Dq][17];
    __shared__ float2 mp[Dq][17];
    __shared__ float2 dp[Dq][17];

    const int tid = threadIdx.x;
    const int row0 = blockIdx.x * RPB;

    // load + impute (coalesced over k)
    for (int i = tid; i < RPB * Dq; i += 256) {
        int r = i >> 6, k = i & 63;
        size_t g = (size_t)(row0 + r) * Dq + k;
        float x = values[g], m = masks[g], dl = deltas[g], xl = xlocf[g];
        float gx = __expf(-fmaxf(fmaf(wgx[k], dl, bgx[k]), 0.f));
        float xi = m * x + (1.f - m) * (gx * xl + (1.f - gx) * emp[k]);
        ((float*)&xp[k][0])[r] = xi;
        ((float*)&mp[k][0])[r] = m;
        ((float*)&dp[k][0])[r] = dl;
    }
    __syncthreads();

    const int j = tid & 127;
    const int half = tid >> 7;
    const int pbase = half * 8;

    ull accZ[8], accR[8], accH[8], accG[8];
    {
        float bzv = bz[j], brv = br[j], bhv = bh[j], bgv = bgh[j];
#pragma unroll
        for (int p = 0; p < 8; p++) {
            accZ[p] = pack2(bzv, bzv);
            accR[p] = pack2(brv, brv);
            accH[p] = pack2(bhv, bhv);
            accG[p] = pack2(bgv, bgv);
        }
    }

#pragma unroll 4
    for (int k = 0; k < Dq; k++) {
        int wi = k * Hq + j;
        ull wgh2 = pack2(wgh[wi], wgh[wi]);
        ull wzx2 = pack2(wzx[wi], wzx[wi]);
        ull wzm2 = pack2(wzm[wi], wzm[wi]);
        ull wrx2 = pack2(wrx[wi], wrx[wi]);
        ull wrm2 = pack2(wrm[wi], wrm[wi]);
        ull whx2 = pack2(whx[wi], whx[wi]);
        ull whm2 = pack2(whm[wi], whm[wi]);
#pragma unroll
        for (int p = 0; p < 8; p++) {
            ull xv = *(const ull*)&xp[k][pbase + p];
            ull mv = *(const ull*)&mp[k][pbase + p];
            ull dv = *(const ull*)&dp[k][pbase + p];
            accG[p] = ffma2(dv, wgh2, accG[p]);
            accZ[p] = ffma2(xv, wzx2, accZ[p]);
            accR[p] = ffma2(xv, wrx2, accR[p]);
            accH[p] = ffma2(xv, whx2, accH[p]);
            accZ[p] = ffma2(mv, wzm2, accZ[p]);
            accR[p] = ffma2(mv, wrm2, accR[p]);
            accH[p] = ffma2(mv, whm2, accH[p]);
        }
    }

#pragma unroll
    for (int p = 0; p < 8; p++) {
        int r0 = half * 16 + 2 * p;
        size_t o0 = (size_t)(row0 + r0) * Hq + j;
        size_t o1 = o0 + Hq;
        float2 vz = unpack2(accZ[p]);
        float2 vr = unpack2(accR[p]);
        float2 vh = unpack2(accH[p]);
        float2 vg = unpack2(accG[p]);
        g_Az[o0] = vz.x;  g_Az[o1] = vz.y;
        g_Ar[o0] = vr.x;  g_Ar[o1] = vr.y;
        g_Ah[o0] = vh.x;  g_Ah[o1] = vh.y;
        g_gh[o0] = __expf(-fmaxf(vg.x, 0.f));
        g_gh[o1] = __expf(-fmaxf(vg.y, 0.f));
    }
}

// ---------------- Phase 2: persistent recurrence ---------------------------
// 128 CTAs x 384 threads; CTA owns 2 batch rows for all T steps.
// warps 0-3 own Wz columns, 4-7 Wr, 8-11 Whh: each thread holds its full
// 128-float weight column as 64 packed f32x2 registers (loaded once).
#define RPC 2
#define GRID2 (Bq / RPC)
#define TH ((size_t)Tq * Hq)

// k-packed dual-row dot product, manually pipelined. h0p/h1p are k-contiguous
// 128-float rows in smem (broadcast loads). w = 64 packed weight pairs.
__device__ __forceinline__ void dot2(const float* __restrict__ h0p,
                                     const float* __restrict__ h1p,
                                     const ull* __restrict__ w,
                                     float init0, float init1,
                                     float& out0, float& out1)
{
    ull a0 = pack2(init0, 0.f), b0 = pack2(0.f, 0.f);
    ull a1 = pack2(init1, 0.f), b1 = pack2(0.f, 0.f);
    ulonglong2 h0 = *(const ulonglong2*)(h0p);
    ulonglong2 h1 = *(const ulonglong2*)(h1p);
#pragma unroll
    for (int q = 0; q < 32; q++) {
        ulonglong2 h0n, h1n;
        if (q < 31) {
            h0n = *(const ulonglong2*)(h0p + 4 * (q + 1));
            h1n = *(const ulonglong2*)(h1p + 4 * (q + 1));
        } else { h0n = h0; h1n = h1; }
        a0 = ffma2(h0.x, w[2 * q], a0);
        b0 = ffma2(h0.y, w[2 * q + 1], b0);
        a1 = ffma2(h1.x, w[2 * q], a1);
        b1 = ffma2(h1.y, w[2 * q + 1], b1);
        h0 = h0n; h1 = h1n;
    }
    float2 fa0 = unpack2(a0), fb0 = unpack2(b0);
    float2 fa1 = unpack2(a1), fb1 = unpack2(b1);
    out0 = (fa0.x + fa0.y) + (fb0.x + fb0.y);
    out1 = (fa1.x + fa1.y) + (fb1.x + fb1.y);
}

__global__ void __launch_bounds__(384, 1) phase2_kernel(
    const float* __restrict__ wzh, const float* __restrict__ wrh,
    const float* __restrict__ whh,
    float* __restrict__ hidden, float* __restrict__ hlast)
{
    __shared__ float hcur[2 * Hq];   // gamma-scaled h (in place)
    __shared__ float rh[2 * Hq];     // r*h
    __shared__ float zs[2 * Hq];     // z gate

    const int tid = threadIdx.x;
    const int g3 = tid >> 7;         // 0=z, 1=r, 2=h  (one warp of each per SMSP)
    const int j = tid & 127;
    const int b0 = blockIdx.x * RPC;

    // load my weight column, packed over k
    const float* W = (g3 == 0) ? wzh : (g3 == 1) ? wrh : whh;
    ull wreg[64];
#pragma unroll
    for (int kp = 0; kp < 64; kp++)
        wreg[kp] = pack2(W[(2 * kp) * Hq + j], W[(2 * kp + 1) * Hq + j]);

    if (tid < 2 * Hq) hcur[tid] = 0.f;

    // per-group A prefetch state (current / next)
    const size_t base00 = (size_t)b0 * TH + j;   // row0, t=0
    float ac0, ac1, ghc = 0.f;
    if (g3 == 0) { ac0 = g_Az[base00]; ac1 = g_Az[base00 + TH]; ghc = g_gh[base00]; }
    else if (g3 == 1) { ac0 = g_Ar[base00]; ac1 = g_Ar[base00 + TH]; ghc = g_gh[base00 + TH]; }
    else { ac0 = g_Ah[base00]; ac1 = g_Ah[base00 + TH]; }

    __syncthreads();

    for (int t = 0; t < Tq; t++) {
        // ---- stage A: gamma-scale h in place (z warp: row0, r warp: row1)
        if (g3 == 0) hcur[j] *= ghc;
        else if (g3 == 1) hcur[Hq + j] *= ghc;
        __syncthreads();  // S1: scaled h visible

        // ---- prefetch t+1 (in flight during both dot phases)
        float an0, an1, ghn = 0.f;
        {
            int tn = (t < Tq - 1) ? t + 1 : t;
            size_t bn = (size_t)b0 * TH + (size_t)tn * Hq + j;
            if (g3 == 0) { an0 = g_Az[bn]; an1 = g_Az[bn + TH]; ghn = g_gh[bn]; }
            else if (g3 == 1) { an0 = g_Ar[bn]; an1 = g_Ar[bn + TH]; ghn = g_gh[bn + TH]; }
            else { an0 = g_Ah[bn]; an1 = g_Ah[bn + TH]; }
        }

        float ah0 = ac0, ah1 = ac1;  // keep for h-warp use after S2

        // ---- z / r dots
        if (g3 == 0) {
            float s0, s1;
            dot2(hcur, hcur + Hq, wreg, ac0, ac1, s0, s1);
            zs[j]      = 1.f / (1.f + __expf(-s0));
            zs[Hq + j] = 1.f / (1.f + __expf(-s1));
        } else if (g3 == 1) {
            float s0, s1;
            dot2(hcur, hcur + Hq, wreg, ac0, ac1, s0, s1);
            float r0 = 1.f / (1.f + __expf(-s0));
            float r1 = 1.f / (1.f + __expf(-s1));
            rh[j]      = r0 * hcur[j];
            rh[Hq + j] = r1 * hcur[Hq + j];
        }
        __syncthreads();  // S2: z, r*h visible

        // ---- h~ + gate update (h warps only)
        if (g3 == 2) {
            float s0, s1;
            dot2(rh, rh + Hq, wreg, ah0, ah1, s0, s1);
            float ht0 = tanhf(s0), ht1 = tanhf(s1);
            float h0v = hcur[j], h1v = hcur[Hq + j];
            float hn0 = fmaf(zs[j],      ht0 - h0v, h0v);
            float hn1 = fmaf(zs[Hq + j], ht1 - h1v, h1v);
            hcur[j] = hn0;
            hcur[Hq + j] = hn1;
            hidden[(size_t)b0 * TH + (size_t)t * Hq + j] = hn0;
            hidden[(size_t)b0 * TH + TH + (size_t)t * Hq + j] = hn1;
        }
        __syncthreads();  // S3: new h visible for next step

        ac0 = an0; ac1 = an1; ghc = ghn;
    }

    if (g3 == 2) {
        hlast[(size_t)b0 * Hq + j]       = hcur[j];
        hlast[(size_t)(b0 + 1) * Hq + j] = hcur[Hq + j];
    }
}

// ---------------- launch ----------------------------------------------------
extern "C" void kernel_launch(void* const* d_in, const int* in_sizes, int n_in,
                              void* d_out, int out_size) {
    const float* values = (const float*)d_in[0];
    const float* masks  = (const float*)d_in[1];
    const float* deltas = (const float*)d_in[2];
    const float* emp    = (const float*)d_in[3];
    const float* xlocf  = (const float*)d_in[4];
    const float* wgx    = (const float*)d_in[5];
    const float* wgh    = (const float*)d_in[6];
    const float* wrx    = (const float*)d_in[7];
    const float* wrh    = (const float*)d_in[8];
    const float* wrm    = (const float*)d_in[9];
    const float* wzx    = (const float*)d_in[10];
    const float* wzh    = (const float*)d_in[11];
    const float* wzm    = (const float*)d_in[12];
    const float* whx    = (const float*)d_in[13];
    const float* whh    = (const float*)d_in[14];
    const float* whm    = (const float*)d_in[15];
    const float* bgx    = (const float*)d_in[16];
    const float* bgh    = (const float*)d_in[17];
    const float* br     = (const float*)d_in[18];
    const float* bz     = (const float*)d_in[19];
    const float* bh     = (const float*)d_in[20];

    float* out = (float*)d_out;
    float* hidden = out;                              // [B, T, H]
    float* hlast = out + (size_t)Bq * Tq * Hq;        // [B, H]

    phase1_kernel<<<NROW / RPB, 256>>>(values, masks, deltas, emp, xlocf,
                                       wgx, bgx, wgh, bgh,
                                       wzx, wzm, bz,
                                       wrx, wrm, br,
                                       whx, whm, bh);

    phase2_kernel<<<GRID2, 384>>>(wzh, wrh, whh, hidden, hlast);
}

// round 8
// speedup vs baseline: 1.2525x; 1.0019x over previous
#include <cuda_runtime.h>
#include <cuda_bf16.h>
#include <cstdint>
#include <cstddef>

#define Bq 256
#define Tq 512
#define Dq 64
#define Hq 128
#define NROW (Bq * Tq)
#define TH ((size_t)Tq * Hq)

typedef unsigned long long ull;

// ---------------- packed f32x2 helpers -------------------------------------
__device__ __forceinline__ ull ffma2(ull a, ull b, ull c) {
    ull d;
    asm("fma.rn.f32x2 %0, %1, %2, %3;" : "=l"(d) : "l"(a), "l"(b), "l"(c));
    return d;
}
__device__ __forceinline__ ull pack2(float lo, float hi) {
    ull d;
    asm("mov.b64 %0, {%1, %2};" : "=l"(d) : "f"(lo), "f"(hi));
    return d;
}
__device__ __forceinline__ float2 unpack2(ull v) {
    float2 r;
    asm("mov.b64 {%0, %1}, %2;" : "=f"(r.x), "=f"(r.y) : "l"(v));
    return r;
}
__device__ __forceinline__ float fast_sigmoid(float x) {
    return __fdividef(1.f, 1.f + __expf(-x));
}

// ---------------- scratch (device globals; no runtime allocation) ----------
__device__ float g_Az[(size_t)NROW * Hq];
__device__ float g_Ar[(size_t)NROW * Hq];
__device__ float g_Ah[(size_t)NROW * Hq];
__device__ float g_gh[(size_t)NROW * Hq];

// ---------------- Phase 1: imputation + input projections ------------------
#define RPB 32
#define P1S 36   // smem row stride in floats (32 data + 4 pad; 16B multiple)

__global__ void __launch_bounds__(256) phase1_kernel(
    const float* __restrict__ values, const float* __restrict__ masks,
    const float* __restrict__ deltas, const float* __restrict__ emp,
    const float* __restrict__ xlocf,
    const float* __restrict__ wgx, const float* __restrict__ bgx,
    const float* __restrict__ wgh, const float* __restrict__ bgh,
    const float* __restrict__ wzx, const float* __restrict__ wzm, const float* __restrict__ bz,
    const float* __restrict__ wrx, const float* __restrict__ wrm, const float* __restrict__ br,
    const float* __restrict__ whx, const float* __restrict__ whm, const float* __restrict__ bh)
{
    __shared__ alignas(16) float sx[Dq * P1S];
    __shared__ alignas(16) float smm[Dq * P1S];
    __shared__ alignas(16) float sd[Dq * P1S];

    const int tid = threadIdx.x;
    const int row0 = blockIdx.x * RPB;

    // load + impute (coalesced over k); element r of row k at sx[k*P1S + r]
    for (int i = tid; i < RPB * Dq; i += 256) {
        int r = i >> 6, k = i & 63;
        size_t g = (size_t)(row0 + r) * Dq + k;
        float x = values[g], m = masks[g], dl = deltas[g], xl = xlocf[g];
        float gx = __expf(-fmaxf(fmaf(wgx[k], dl, bgx[k]), 0.f));
        float xi = m * x + (1.f - m) * (gx * xl + (1.f - gx) * emp[k]);
        sx[k * P1S + r] = xi;
        smm[k * P1S + r] = m;
        sd[k * P1S + r] = dl;
    }
    __syncthreads();

    const int j = tid & 127;
    const int half = tid >> 7;          // which 16-row half
    const int fofs = half * 16;         // float offset within a smem row

    ull accZ[8], accR[8], accH[8], accG[8];
    {
        float bzv = bz[j], brv = br[j], bhv = bh[j], bgv = bgh[j];
#pragma unroll
        for (int p = 0; p < 8; p++) {
            accZ[p] = pack2(bzv, bzv);
            accR[p] = pack2(brv, brv);
            accH[p] = pack2(bhv, bhv);
            accG[p] = pack2(bgv, bgv);
        }
    }

#pragma unroll 4
    for (int k = 0; k < Dq; k++) {
        int wi = k * Hq + j;
        ull wgh2 = pack2(wgh[wi], wgh[wi]);
        ull wzx2 = pack2(wzx[wi], wzx[wi]);
        ull wzm2 = pack2(wzm[wi], wzm[wi]);
        ull wrx2 = pack2(wrx[wi], wrx[wi]);
        ull wrm2 = pack2(wrm[wi], wrm[wi]);
        ull whx2 = pack2(whx[wi], whx[wi]);
        ull whm2 = pack2(whm[wi], whm[wi]);
        const ulonglong2* x2 = (const ulonglong2*)(sx + k * P1S + fofs);
        const ulonglong2* m2 = (const ulonglong2*)(smm + k * P1S + fofs);
        const ulonglong2* d2 = (const ulonglong2*)(sd + k * P1S + fofs);
#pragma unroll
        for (int q = 0; q < 4; q++) {
            ulonglong2 xv = x2[q];
            ulonglong2 mv = m2[q];
            ulonglong2 dv = d2[q];
            accG[2 * q]     = ffma2(dv.x, wgh2, accG[2 * q]);
            accG[2 * q + 1] = ffma2(dv.y, wgh2, accG[2 * q + 1]);
            accZ[2 * q]     = ffma2(xv.x, wzx2, accZ[2 * q]);
            accZ[2 * q + 1] = ffma2(xv.y, wzx2, accZ[2 * q + 1]);
            accR[2 * q]     = ffma2(xv.x, wrx2, accR[2 * q]);
            accR[2 * q + 1] = ffma2(xv.y, wrx2, accR[2 * q + 1]);
            accH[2 * q]     = ffma2(xv.x, whx2, accH[2 * q]);
            accH[2 * q + 1] = ffma2(xv.y, whx2, accH[2 * q + 1]);
            accZ[2 * q]     = ffma2(mv.x, wzm2, accZ[2 * q]);
            accZ[2 * q + 1] = ffma2(mv.y, wzm2, accZ[2 * q + 1]);
            accR[2 * q]     = ffma2(mv.x, wrm2, accR[2 * q]);
            accR[2 * q + 1] = ffma2(mv.y, wrm2, accR[2 * q + 1]);
            accH[2 * q]     = ffma2(mv.x, whm2, accH[2 * q]);
            accH[2 * q + 1] = ffma2(mv.y, whm2, accH[2 * q + 1]);
        }
    }

#pragma unroll
    for (int p = 0; p < 8; p++) {
        int r0 = half * 16 + 2 * p;
        size_t o0 = (size_t)(row0 + r0) * Hq + j;
        size_t o1 = o0 + Hq;
        float2 vz = unpack2(accZ[p]);
        float2 vr = unpack2(accR[p]);
        float2 vh = unpack2(accH[p]);
        float2 vg = unpack2(accG[p]);
        g_Az[o0] = vz.x;  g_Az[o1] = vz.y;
        g_Ar[o0] = vr.x;  g_Ar[o1] = vr.y;
        g_Ah[o0] = vh.x;  g_Ah[o1] = vh.y;
        g_gh[o0] = __expf(-fmaxf(vg.x, 0.f));
        g_gh[o1] = __expf(-fmaxf(vg.y, 0.f));
    }
}

// ---------------- Phase 2: persistent recurrence (pipelined over rows) -----
// 128 CTAs x 384 threads; CTA owns 2 independent batch rows.
// Warp groups: g=0 -> z (Wz in regs), g=1 -> r (Wr), g=2 -> h (Whh).
// Slot schedule (one barrier per slot):
//   slot s: z/r warps compute gates for index s = (row = s&1, t = s>>1)
//           h warps compute h~/update for index s-1                  [s >= 1]
// The a_c/a_n shift runs every slot, so a_c(s) = value prefetched at s-2
// (or from init). z/r consume index s -> init a_c=idx0, a_n=idx1, prefetch
// at s loads idx(s+2). h consumes index s-1 -> init a_n=idx0 (a_c unused),
// prefetch at s loads idx(s+1).
// Gamma-scaling of h is folded into the h-warp epilogue (multiply by the
// NEXT step's gamma before publishing), so hcur always holds scaled h.
#define RPC 2
#define GRID2 (Bq / RPC)

__device__ __forceinline__ float dot1(const float* __restrict__ hp,
                                      const ull* __restrict__ w, float init)
{
    ull a = pack2(init, 0.f);
    ull b = pack2(0.f, 0.f);
    ull c = b, d = b;
#pragma unroll
    for (int q = 0; q < 16; q++) {
        ulonglong2 h0 = *(const ulonglong2*)(hp + 8 * q);
        ulonglong2 h1 = *(const ulonglong2*)(hp + 8 * q + 4);
        a = ffma2(h0.x, w[4 * q + 0], a);
        b = ffma2(h0.y, w[4 * q + 1], b);
        c = ffma2(h1.x, w[4 * q + 2], c);
        d = ffma2(h1.y, w[4 * q + 3], d);
    }
    float2 fa = unpack2(a), fb = unpack2(b), fc = unpack2(c), fd = unpack2(d);
    return ((fa.x + fa.y) + (fb.x + fb.y)) + ((fc.x + fc.y) + (fd.x + fd.y));
}

__global__ void __launch_bounds__(384, 1) phase2_kernel(
    const float* __restrict__ wzh, const float* __restrict__ wrh,
    const float* __restrict__ whh,
    float* __restrict__ hidden, float* __restrict__ hlast)
{
    __shared__ alignas(16) float hcur[2][Hq];   // gamma-scaled hidden state
    __shared__ alignas(16) float rh[2][Hq];     // r * h
    __shared__ alignas(16) float zs[2][Hq];     // z gate

    const int tid = threadIdx.x;
    const int g3 = tid >> 7;        // 0=z, 1=r, 2=h
    const int j = tid & 127;
    const int b0 = blockIdx.x * RPC;

    // register-resident weight column (packed over k)
    const float* W = (g3 == 0) ? wzh : (g3 == 1) ? wrh : whh;
    ull wreg[64];
#pragma unroll
    for (int kp = 0; kp < 64; kp++)
        wreg[kp] = pack2(W[(2 * kp) * Hq + j], W[(2 * kp + 1) * Hq + j]);

    if (tid < 2 * Hq) ((float*)hcur)[tid] = 0.f;

    const size_t r0base = (size_t)b0 * TH + j;       // (row0, t=0)
    const size_t r1base = r0base + TH;               // (row1, t=0)

    // prefetch state: after the end-of-slot shift, a_c(s) = value that was in
    // a_n at slot s-1. See schedule comment above for the init derivation.
    float a_c, a_n, gh_c = 1.f, gh_n = 1.f;
    if (g3 == 0)      { a_c = g_Az[r0base]; a_n = g_Az[r1base]; }
    else if (g3 == 1) { a_c = g_Ar[r0base]; a_n = g_Ar[r1base]; }
    else {
        // h consumes idx0 at slot 1 -> that value must sit in a_n at init.
        a_c = 0.f;           gh_c = 1.f;                    // unused (slot 0)
        a_n = g_Ah[r0base];  gh_n = g_gh[r0base + Hq];      // gamma(row0, t=1)
    }

    __syncthreads();

    const int NSLOT = 2 * Tq;   // slots 0..NSLOT inclusive
    for (int s = 0; s <= NSLOT; s++) {
        // ---- prefetch (hidden behind this slot's dot)
        float a_nn = 0.f, gh_nn = 1.f;
        if (g3 < 2) {
            // feeds slot s+2 -> index s+2 = (row = s&1, t = (s>>1)+1)
            if (s + 2 < NSLOT) {
                int row = s & 1, t = (s >> 1) + 1;
                size_t ix = (size_t)(b0 + row) * TH + (size_t)t * Hq + j;
                a_nn = (g3 == 0) ? g_Az[ix] : g_Ar[ix];
            }
        } else {
            // feeds slot s+2 -> h consumes index s+1 there
            if (s + 1 < NSLOT) {
                int row = (s + 1) & 1, t = (s + 1) >> 1;
                size_t ix = (size_t)(b0 + row) * TH + (size_t)t * Hq + j;
                a_nn = g_Ah[ix];
                gh_nn = (t + 1 < Tq) ? g_gh[ix + Hq] : 1.f;
            }
        }

        if (g3 < 2) {
            if (s < NSLOT) {
                int row = s & 1;
                float sum = dot1(&hcur[row][0], wreg, a_c);
                float sg = fast_sigmoid(sum);
                if (g3 == 0) zs[row][j] = sg;
                else         rh[row][j] = sg * hcur[row][j];
            }
        } else {
            if (s >= 1) {
                int row = (s - 1) & 1;
                int t = (s - 1) >> 1;
                float sum = dot1(&rh[row][0], wreg, a_c);
                // tanh(x) = 2*sigmoid(2x) - 1  (overflow-safe)
                float ht = fmaf(2.f, fast_sigmoid(2.f * sum), -1.f);
                float hv = hcur[row][j];
                float hn = fmaf(zs[row][j], ht - hv, hv);
                hidden[(size_t)(b0 + row) * TH + (size_t)t * Hq + j] = hn;
                hcur[row][j] = hn * gh_c;   // pre-scale by gamma(t+1)
            }
        }

        a_c = a_n;  a_n = a_nn;
        gh_c = gh_n; gh_n = gh_nn;
        __syncthreads();
    }

    if (g3 == 2) {
        // hcur holds unscaled final h (last gamma multiplier was 1.0)
        hlast[(size_t)b0 * Hq + j]       = hcur[0][j];
        hlast[(size_t)(b0 + 1) * Hq + j] = hcur[1][j];
    }
}

// ---------------- launch ----------------------------------------------------
extern "C" void kernel_launch(void* const* d_in, const int* in_sizes, int n_in,
                              void* d_out, int out_size) {
    const float* values = (const float*)d_in[0];
    const float* masks  = (const float*)d_in[1];
    const float* deltas = (const float*)d_in[2];
    const float* emp    = (const float*)d_in[3];
    const float* xlocf  = (const float*)d_in[4];
    const float* wgx    = (const float*)d_in[5];
    const float* wgh    = (const float*)d_in[6];
    const float* wrx    = (const float*)d_in[7];
    const float* wrh    = (const float*)d_in[8];
    const float* wrm    = (const float*)d_in[9];
    const float* wzx    = (const float*)d_in[10];
    const float* wzh    = (const float*)d_in[11];
    const float* wzm    = (const float*)d_in[12];
    const float* whx    = (const float*)d_in[13];
    const float* whh    = (const float*)d_in[14];
    const float* whm    = (const float*)d_in[15];
    const float* bgx    = (const float*)d_in[16];
    const float* bgh    = (const float*)d_in[17];
    const float* br     = (const float*)d_in[18];
    const float* bz     = (const float*)d_in[19];
    const float* bh     = (const float*)d_in[20];

    float* out = (float*)d_out;
    float* hidden = out;                              // [B, T, H]
    float* hlast = out + (size_t)Bq * Tq * Hq;        // [B, H]

    phase1_kernel<<<NROW / RPB, 256>>>(values, masks, deltas, emp, xlocf,
                                       wgx, bgx, wgh, bgh,
                                       wzx, wzm, bz,
                                       wrx, wrm, br,
                                       whx, whm, bh);

    phase2_kernel<<<GRID2, 384>>>(wzh, wrh, whh, hidden, hlast);
}